// round 9
// baseline (speedup 1.0000x reference)
#include <cuda_runtime.h>
#include <cuda_fp16.h>
#include <cstdint>

#define THREADS 256
#define NOUT 128
#define KLOG 84
#define M_TILE 64
#define SA_STRIDE 208              // bytes per A row (104 halves: 96 k + pad)
#define SA_BUF    (M_TILE * SA_STRIDE)   // 13312
#define SMEM_TOTAL (2 * SA_BUF)          // double buffered: 26624 B

__device__ __forceinline__ uint32_t smem_u32(const void* p) {
    return (uint32_t)__cvta_generic_to_shared(p);
}

__device__ __forceinline__ uint32_t pack_h2(float a, float b) {
    __half2 h = __floats2half2_rn(a, b);
    return *reinterpret_cast<uint32_t*>(&h);
}

__device__ __forceinline__ uint4 pack8h(const float* x) {
    return make_uint4(pack_h2(x[0], x[1]), pack_h2(x[2], x[3]),
                      pack_h2(x[4], x[5]), pack_h2(x[6], x[7]));
}

#define LDSM_X4(r0, r1, r2, r3, addr)                                          \
    asm volatile("ldmatrix.sync.aligned.m8n8.x4.shared.b16 {%0,%1,%2,%3}, [%4];" \
                 : "=r"(r0), "=r"(r1), "=r"(r2), "=r"(r3) : "r"(addr))

#define MMA16816(c, a, b)                                                      \
    asm volatile("mma.sync.aligned.m16n8k16.row.col.f32.f16.f16.f32 "          \
                 "{%0,%1,%2,%3}, {%4,%5,%6,%7}, {%8,%9}, {%0,%1,%2,%3};"       \
                 : "+f"((c)[0]), "+f"((c)[1]), "+f"((c)[2]), "+f"((c)[3])      \
                 : "r"((a)[0]), "r"((a)[1]), "r"((a)[2]), "r"((a)[3]),         \
                   "r"((b)[0]), "r"((b)[1]))

__device__ __forceinline__ void prefetch(const float* __restrict__ bond_feat,
                                         const void* __restrict__ bidx, int is64,
                                         const float* __restrict__ pos,
                                         long long E, long long tile, int tid,
                                         float4 f[4], float& dist) {
    long long tbase = tile << 6;
    int e = tid >> 2, q = tid & 3;            // 4 threads per edge row
    long long eg = tbase + e;
    if (eg >= E) eg = E - 1;
    const float4* src = reinterpret_cast<const float4*>(bond_feat) + eg * 16 + q * 4;
#pragma unroll
    for (int p = 0; p < 4; p++) f[p] = src[p];
    if (tid < M_TILE) {
        long long eg2 = tbase + tid;
        if (eg2 >= E) eg2 = E - 1;
        long long i0, i1;
        if (is64) {
            const long long* b = (const long long*)bidx;
            i0 = b[eg2]; i1 = b[E + eg2];
        } else {
            const int* b = (const int*)bidx;
            i0 = (long long)b[eg2]; i1 = (long long)b[E + eg2];
        }
        float dx = pos[i0 * 3 + 0] - pos[i1 * 3 + 0];
        float dy = pos[i0 * 3 + 1] - pos[i1 * 3 + 1];
        float dz = pos[i0 * 3 + 2] - pos[i1 * 3 + 2];
        dist = sqrtf(dx * dx + dy * dy + dz * dz);
    }
}

__device__ __forceinline__ void fill_tile(char* sA, const float4 f[4], float dist, int tid) {
    int e = tid >> 2, q = tid & 3;
    int rb = e * SA_STRIDE + q * 32;
    float xs0[8] = { f[0].x, f[0].y, f[0].z, f[0].w, f[1].x, f[1].y, f[1].z, f[1].w };
    float xs1[8] = { f[2].x, f[2].y, f[2].z, f[2].w, f[3].x, f[3].y, f[3].z, f[3].w };
    *reinterpret_cast<uint4*>(sA + rb)      = pack8h(xs0);
    *reinterpret_cast<uint4*>(sA + rb + 16) = pack8h(xs1);
    if (tid < M_TILE) {
        float gg[20];
        const float delta = 10.0f / 19.0f;
        const float coeff = -0.5f / (delta * delta);
#pragma unroll
        for (int j = 0; j < 20; j++) {
            float d = dist - (float)j * delta;
            gg[j] = __expf(coeff * d * d);
        }
        int row = tid * SA_STRIDE;
        *reinterpret_cast<uint4*>(sA + row + 128) = pack8h(gg);
        *reinterpret_cast<uint4*>(sA + row + 144) = pack8h(gg + 8);
        *reinterpret_cast<uint2*>(sA + row + 160) =
            make_uint2(pack_h2(gg[16], gg[17]), pack_h2(gg[18], gg[19]));
    }
}

__global__ void __launch_bounds__(THREADS, 2)
bond_embed_mma(const float* __restrict__ bond_feat,
               const void* __restrict__ bond_index,
               const float* __restrict__ pos,
               const float* __restrict__ W,
               const float* __restrict__ bias,
               float* __restrict__ out,
               long long E) {
    extern __shared__ char smem[];
    const uint32_t sb = smem_u32(smem);
    const int tid = threadIdx.x;
    const int warp = tid >> 5, lane = tid & 31;
    const int mgrp = warp >> 2, ng = warp & 3;   // 2 m-groups x 4 n-groups
    const int g = lane >> 2, tg = lane & 3;

    // inline int64-vs-int32 index detection: for int64 indices (<1e5) the odd
    // 32-bit words of the first 8 entries are all zero; for random int32
    // indices P(all zero) ~ 1e-40. Uniform across all threads/CTAs.
    int is64;
    {
        const uint2* bx = (const uint2*)bond_index;
        unsigned z = 0;
#pragma unroll
        for (int p = 0; p < 8; p++) z |= bx[p].y;
        is64 = (z == 0);
    }

    // zero both A buffers (covers k-pad 84..103; fills touch k 0..83 only)
    for (int o = tid * 16; o < SMEM_TOTAL; o += THREADS * 16)
        *reinterpret_cast<uint4*>(smem + o) = make_uint4(0, 0, 0, 0);

    // B fragments in registers with COLUMN-PERMUTED packing:
    // fragment slot (nb, g) holds W column ng*32 + P(nb*8+g), where
    // P(nb*8+r) = (r>>1)*8 + 2*nb + (r&1). Then the MMA's D ownership
    // (thread tg owns hw-cols nb*8+2tg+p) lands on OUTPUT columns
    // tg*8 + 2*nb + p — 8 consecutive columns per thread, no transpose.
    uint32_t bfr[6][4][2];
#pragma unroll
    for (int ks = 0; ks < 6; ks++)
#pragma unroll
        for (int nb = 0; nb < 4; nb++) {
            int n = ng * 32 + (g >> 1) * 8 + 2 * nb + (g & 1);
#pragma unroll
            for (int p = 0; p < 2; p++) {
                int k = ks * 16 + tg * 2 + p * 8;
                float w0 = (k < KLOG) ? W[k * NOUT + n] : 0.0f;
                float w1 = (k + 1 < KLOG) ? W[(k + 1) * NOUT + n] : 0.0f;
                bfr[ks][nb][p] = pack_h2(w0, w1);
            }
        }
    // bias for this thread's output columns: ng*32 + tg*8 .. +7
    float4 bv0 = *reinterpret_cast<const float4*>(bias + ng * 32 + tg * 8);
    float4 bv1 = *reinterpret_cast<const float4*>(bias + ng * 32 + tg * 8 + 4);

    __syncthreads();

    const long long nT = (E + M_TILE - 1) >> 6;
    const long long stride = (long long)gridDim.x;
    long long tile = (long long)blockIdx.x;

    float4 f[4];
    float dist = 0.0f;
    if (tile < nT)
        prefetch(bond_feat, bond_index, is64, pos, E, tile, tid, f, dist);

    const int rowoff = (mgrp * 32 + (lane & 15)) * SA_STRIDE + (lane >> 4) * 16;

    int i = 0;
    for (; tile < nT; tile += stride, ++i) {
        const int buf = i & 1;
        fill_tile(smem + buf * SA_BUF, f, dist, tid);
        if (tile + stride < nT)
            prefetch(bond_feat, bond_index, is64, pos, E, tile + stride, tid, f, dist);

        __syncthreads();

        float acc[2][4][4];
#pragma unroll
        for (int mb = 0; mb < 2; mb++)
#pragma unroll
            for (int nb = 0; nb < 4; nb++)
#pragma unroll
                for (int r = 0; r < 4; r++) acc[mb][nb][r] = 0.0f;

        const uint32_t abase = sb + (uint32_t)buf * SA_BUF + (uint32_t)rowoff;
#pragma unroll
        for (int ks = 0; ks < 6; ks++) {
            uint32_t ah[2][4];
#pragma unroll
            for (int mb = 0; mb < 2; mb++) {
                uint32_t ad = abase + (uint32_t)(mb * 16 * SA_STRIDE + ks * 32);
                LDSM_X4(ah[mb][0], ah[mb][1], ah[mb][2], ah[mb][3], ad);
            }
#pragma unroll
            for (int mb = 0; mb < 2; mb++)
#pragma unroll
                for (int nb = 0; nb < 4; nb++)
                    MMA16816(acc[mb][nb], ah[mb], bfr[ks][nb]);
        }

        // Epilogue: thanks to the B column permutation,
        // acc[mb][nb][2*rh+p] = OUT[row][ng*32 + tg*8 + 2*nb + p].
        // Assemble two float4 and store 2x STG.128 per row — no shuffles.
        long long tb = tile << 6;
#pragma unroll
        for (int mb = 0; mb < 2; mb++) {
#pragma unroll
            for (int rh = 0; rh < 2; rh++) {
                long long e = tb + mgrp * 32 + mb * 16 + rh * 8 + g;
                if (e < E) {
                    float4 r0 = make_float4(acc[mb][0][2*rh]   + bv0.x,
                                            acc[mb][0][2*rh+1] + bv0.y,
                                            acc[mb][1][2*rh]   + bv0.z,
                                            acc[mb][1][2*rh+1] + bv0.w);
                    float4 r1 = make_float4(acc[mb][2][2*rh]   + bv1.x,
                                            acc[mb][2][2*rh+1] + bv1.y,
                                            acc[mb][3][2*rh]   + bv1.z,
                                            acc[mb][3][2*rh+1] + bv1.w);
                    float4* op = reinterpret_cast<float4*>(out + e * NOUT + ng * 32 + tg * 8);
                    op[0] = r0;
                    op[1] = r1;
                }
            }
        }
    }
}

extern "C" void kernel_launch(void* const* d_in, const int* in_sizes, int n_in,
                              void* d_out, int out_size) {
    const float* bond_feat  = (const float*)d_in[0];
    const void*  bond_index = (const void*)d_in[1];
    const float* pos        = (const float*)d_in[2];
    const float* W          = (const float*)d_in[3];
    const float* bias       = (const float*)d_in[4];
    float* out = (float*)d_out;

    long long E = (long long)(in_sizes[0] / 64);
    long long nT = (E + M_TILE - 1) >> 6;
    int grid = (int)(nT < 296 ? nT : 296);

    cudaFuncSetAttribute(bond_embed_mma,
                         cudaFuncAttributeMaxDynamicSharedMemorySize, SMEM_TOTAL);

    bond_embed_mma<<<grid, THREADS, SMEM_TOTAL>>>(bond_feat, bond_index, pos, W, bias, out, E);
}

// round 10
// speedup vs baseline: 1.2355x; 1.2355x over previous
#include <cuda_runtime.h>
#include <cuda_fp16.h>
#include <cstdint>

#define THREADS 128
#define NOUT 128
#define KLOG 84
#define M_TILE 32
#define SA_STRIDE 208              // bytes per A row (104 halves: 96 k + pad)
#define SA_BUF    (M_TILE * SA_STRIDE)   // 6656
#define SMEM_TOTAL (2 * SA_BUF)          // double buffered: 13312 B

__device__ __forceinline__ uint32_t smem_u32(const void* p) {
    return (uint32_t)__cvta_generic_to_shared(p);
}

__device__ __forceinline__ uint32_t pack_h2(float a, float b) {
    __half2 h = __floats2half2_rn(a, b);
    return *reinterpret_cast<uint32_t*>(&h);
}

__device__ __forceinline__ uint4 pack8h(const float* x) {
    return make_uint4(pack_h2(x[0], x[1]), pack_h2(x[2], x[3]),
                      pack_h2(x[4], x[5]), pack_h2(x[6], x[7]));
}

#define LDSM_X4(r0, r1, r2, r3, addr)                                          \
    asm volatile("ldmatrix.sync.aligned.m8n8.x4.shared.b16 {%0,%1,%2,%3}, [%4];" \
                 : "=r"(r0), "=r"(r1), "=r"(r2), "=r"(r3) : "r"(addr))

#define MMA16816(c, a, b)                                                      \
    asm volatile("mma.sync.aligned.m16n8k16.row.col.f32.f16.f16.f32 "          \
                 "{%0,%1,%2,%3}, {%4,%5,%6,%7}, {%8,%9}, {%0,%1,%2,%3};"       \
                 : "+f"((c)[0]), "+f"((c)[1]), "+f"((c)[2]), "+f"((c)[3])      \
                 : "r"((a)[0]), "r"((a)[1]), "r"((a)[2]), "r"((a)[3]),         \
                   "r"((b)[0]), "r"((b)[1]))

__device__ __forceinline__ void prefetch(const float* __restrict__ bond_feat,
                                         const void* __restrict__ bidx, int is64,
                                         const float* __restrict__ pos,
                                         long long E, long long tile, int tid,
                                         float4 f[4], float& dist) {
    long long tbase = tile << 5;
    int e = tid >> 2, q = tid & 3;            // 4 threads per edge row
    long long eg = tbase + e;
    if (eg >= E) eg = E - 1;
    const float4* src = reinterpret_cast<const float4*>(bond_feat) + eg * 16 + q * 4;
#pragma unroll
    for (int p = 0; p < 4; p++) f[p] = src[p];
    if (tid < M_TILE) {
        long long eg2 = tbase + tid;
        if (eg2 >= E) eg2 = E - 1;
        long long i0, i1;
        if (is64) {
            const long long* b = (const long long*)bidx;
            i0 = b[eg2]; i1 = b[E + eg2];
        } else {
            const int* b = (const int*)bidx;
            i0 = (long long)b[eg2]; i1 = (long long)b[E + eg2];
        }
        float dx = pos[i0 * 3 + 0] - pos[i1 * 3 + 0];
        float dy = pos[i0 * 3 + 1] - pos[i1 * 3 + 1];
        float dz = pos[i0 * 3 + 2] - pos[i1 * 3 + 2];
        dist = sqrtf(dx * dx + dy * dy + dz * dz);
    }
}

__device__ __forceinline__ void fill_tile(char* sA, const float4 f[4], float dist, int tid) {
    int e = tid >> 2, q = tid & 3;
    int rb = e * SA_STRIDE + q * 32;
    float xs0[8] = { f[0].x, f[0].y, f[0].z, f[0].w, f[1].x, f[1].y, f[1].z, f[1].w };
    float xs1[8] = { f[2].x, f[2].y, f[2].z, f[2].w, f[3].x, f[3].y, f[3].z, f[3].w };
    *reinterpret_cast<uint4*>(sA + rb)      = pack8h(xs0);
    *reinterpret_cast<uint4*>(sA + rb + 16) = pack8h(xs1);
    if (tid < M_TILE) {
        float gg[20];
        const float delta = 10.0f / 19.0f;
        const float coeff = -0.5f / (delta * delta);
#pragma unroll
        for (int j = 0; j < 20; j++) {
            float d = dist - (float)j * delta;
            gg[j] = __expf(coeff * d * d);
        }
        int row = tid * SA_STRIDE;
        *reinterpret_cast<uint4*>(sA + row + 128) = pack8h(gg);
        *reinterpret_cast<uint4*>(sA + row + 144) = pack8h(gg + 8);
        *reinterpret_cast<uint2*>(sA + row + 160) =
            make_uint2(pack_h2(gg[16], gg[17]), pack_h2(gg[18], gg[19]));
    }
}

// 4x4 quartet transpose over register slots A[0..3], compile-time names only.
#define QTRANSPOSE(A0, A1, A2, A3, tg)                                         \
    do {                                                                       \
        float _s, _x;                                                          \
        _s = ((tg) & 1) ? (A0) : (A1);                                         \
        _x = __shfl_xor_sync(0xffffffffu, _s, 1);                              \
        (A0) = ((tg) & 1) ? _x : (A0);  (A1) = ((tg) & 1) ? (A1) : _x;         \
        _s = ((tg) & 1) ? (A2) : (A3);                                         \
        _x = __shfl_xor_sync(0xffffffffu, _s, 1);                              \
        (A2) = ((tg) & 1) ? _x : (A2);  (A3) = ((tg) & 1) ? (A3) : _x;         \
        _s = ((tg) & 2) ? (A0) : (A2);                                         \
        _x = __shfl_xor_sync(0xffffffffu, _s, 2);                              \
        (A0) = ((tg) & 2) ? _x : (A0);  (A2) = ((tg) & 2) ? (A2) : _x;         \
        _s = ((tg) & 2) ? (A1) : (A3);                                         \
        _x = __shfl_xor_sync(0xffffffffu, _s, 2);                              \
        (A1) = ((tg) & 2) ? _x : (A1);  (A3) = ((tg) & 2) ? (A3) : _x;         \
    } while (0)

__global__ void __launch_bounds__(THREADS, 4)
bond_embed_mma(const float* __restrict__ bond_feat,
               const void* __restrict__ bond_index,
               const float* __restrict__ pos,
               const float* __restrict__ W,
               const float* __restrict__ bias,
               float* __restrict__ out,
               long long E) {
    extern __shared__ char smem[];
    const uint32_t sb = smem_u32(smem);
    const int tid = threadIdx.x;
    const int lane = tid & 31;
    const int ng = (tid >> 5) & 3;               // 4 warps = 4 n-groups, 1 m-group
    const int g = lane >> 2, tg = lane & 3;

    // inline int64-vs-int32 index detection: for int64 indices (<1e5) the odd
    // 32-bit words of the first 8 entries are all zero; for random int32
    // indices P(all zero) ~ 1e-40. Uniform across all threads/CTAs.
    int is64;
    {
        const uint2* bx = (const uint2*)bond_index;
        unsigned z = 0;
#pragma unroll
        for (int p = 0; p < 8; p++) z |= bx[p].y;
        is64 = (z == 0);
    }

    // zero both A buffers (covers k-pad 84..103; fills touch k 0..83 only)
    for (int o = tid * 16; o < SMEM_TOTAL; o += THREADS * 16)
        *reinterpret_cast<uint4*>(smem + o) = make_uint4(0, 0, 0, 0);

    // B fragments in registers (constant across tiles): 6 ksteps x 4 nblocks x 2
    uint32_t bfr[6][4][2];
#pragma unroll
    for (int ks = 0; ks < 6; ks++)
#pragma unroll
        for (int nb = 0; nb < 4; nb++) {
            int n = ng * 32 + nb * 8 + g;
#pragma unroll
            for (int p = 0; p < 2; p++) {
                int k = ks * 16 + tg * 2 + p * 8;
                float w0 = (k < KLOG) ? W[k * NOUT + n] : 0.0f;
                float w1 = (k + 1 < KLOG) ? W[(k + 1) * NOUT + n] : 0.0f;
                bfr[ks][nb][p] = pack_h2(w0, w1);
            }
        }
    // bias for this thread's post-transpose columns: ng*32 + tg*8 .. +7
    float4 bv0 = *reinterpret_cast<const float4*>(bias + ng * 32 + tg * 8);
    float4 bv1 = *reinterpret_cast<const float4*>(bias + ng * 32 + tg * 8 + 4);

    __syncthreads();

    const long long nT = (E + M_TILE - 1) >> 5;
    const long long stride = (long long)gridDim.x;
    long long tile = (long long)blockIdx.x;

    float4 f[4];
    float dist = 0.0f;
    if (tile < nT)
        prefetch(bond_feat, bond_index, is64, pos, E, tile, tid, f, dist);

    const int rowoff = (lane & 15) * SA_STRIDE + (lane >> 4) * 16;

    int i = 0;
    for (; tile < nT; tile += stride, ++i) {
        const int buf = i & 1;
        fill_tile(smem + buf * SA_BUF, f, dist, tid);
        if (tile + stride < nT)
            prefetch(bond_feat, bond_index, is64, pos, E, tile + stride, tid, f, dist);

        __syncthreads();

        float acc[2][4][4];
#pragma unroll
        for (int mb = 0; mb < 2; mb++)
#pragma unroll
            for (int nb = 0; nb < 4; nb++)
#pragma unroll
                for (int r = 0; r < 4; r++) acc[mb][nb][r] = 0.0f;

        const uint32_t abase = sb + (uint32_t)buf * SA_BUF + (uint32_t)rowoff;
#pragma unroll
        for (int ks = 0; ks < 6; ks++) {
            uint32_t ah[2][4];
#pragma unroll
            for (int mb = 0; mb < 2; mb++) {
                uint32_t ad = abase + (uint32_t)(mb * 16 * SA_STRIDE + ks * 32);
                LDSM_X4(ah[mb][0], ah[mb][1], ah[mb][2], ah[mb][3], ad);
            }
#pragma unroll
            for (int mb = 0; mb < 2; mb++)
#pragma unroll
                for (int nb = 0; nb < 4; nb++)
                    MMA16816(acc[mb][nb], ah[mb], bfr[ks][nb]);
        }

        // Epilogue: butterfly transpose (nb <-> tg), then 2x STG.128 per row.
        long long tb = tile << 5;
#pragma unroll
        for (int mb = 0; mb < 2; mb++) {
#pragma unroll
            for (int rh = 0; rh < 2; rh++) {
                QTRANSPOSE(acc[mb][0][2*rh], acc[mb][1][2*rh],
                           acc[mb][2][2*rh], acc[mb][3][2*rh], tg);
                QTRANSPOSE(acc[mb][0][2*rh+1], acc[mb][1][2*rh+1],
                           acc[mb][2][2*rh+1], acc[mb][3][2*rh+1], tg);
                long long e = tb + mb * 16 + rh * 8 + g;
                if (e < E) {
                    float4 r0 = make_float4(acc[mb][0][2*rh]   + bv0.x,
                                            acc[mb][0][2*rh+1] + bv0.y,
                                            acc[mb][1][2*rh]   + bv0.z,
                                            acc[mb][1][2*rh+1] + bv0.w);
                    float4 r1 = make_float4(acc[mb][2][2*rh]   + bv1.x,
                                            acc[mb][2][2*rh+1] + bv1.y,
                                            acc[mb][3][2*rh]   + bv1.z,
                                            acc[mb][3][2*rh+1] + bv1.w);
                    float4* op = reinterpret_cast<float4*>(out + e * NOUT + ng * 32 + tg * 8);
                    op[0] = r0;
                    op[1] = r1;
                }
            }
        }
    }
}

extern "C" void kernel_launch(void* const* d_in, const int* in_sizes, int n_in,
                              void* d_out, int out_size) {
    const float* bond_feat  = (const float*)d_in[0];
    const void*  bond_index = (const void*)d_in[1];
    const float* pos        = (const float*)d_in[2];
    const float* W          = (const float*)d_in[3];
    const float* bias       = (const float*)d_in[4];
    float* out = (float*)d_out;

    long long E = (long long)(in_sizes[0] / 64);
    long long nT = (E + M_TILE - 1) >> 5;
    int grid = (int)(nT < 592 ? nT : 592);

    cudaFuncSetAttribute(bond_embed_mma,
                         cudaFuncAttributeMaxDynamicSharedMemorySize, SMEM_TOTAL);

    bond_embed_mma<<<grid, THREADS, SMEM_TOTAL>>>(bond_feat, bond_index, pos, W, bias, out, E);
}